// round 12
// baseline (speedup 1.0000x reference)
#include <cuda_runtime.h>
#include <cuda_fp16.h>
#include <stdint.h>
#include <math.h>

#define BATCH  16384
#define HID    128
#define SEQ    28
#define INDIM  28
#define OUTDIM 10
#define MR     64       // batch rows per CTA (1 CTA/SM, 512 threads)
#define NT     512
#define HSTRIDE 272     // h tile row stride bytes (136 fp16) — ldsm conflict-free
#define XSTRIDE 80      // x tile row stride bytes
#define HT_SZ  (MR * HSTRIDE)            // 17408 B per h tile
#define SM_X   (4 * HT_SZ)               // x tiles after 4 h tiles
#define XBUF_SZ (MR * XSTRIDE)           // one x buffer
#define SMEM_BYTES (SM_X + 2 * XBUF_SZ)  // 79872

// h tile offset: layer L, buffer b
#define HT_OFF(L, b) (((L) * 2 + (b)) * HT_SZ)

// ---- prepped weights: exact mma.m16n8k16 B-fragment order, single fp16 ----
// layout per matrix section: [wn*KS + ks][lane][16 regs(uint32)]
// reg r = nf*2 + b : packed fp16 pair (k0, k0+1), k0 = ks*16 + (lane&3)*2 + b*8,
//                    n'' = wn*64 + nf*8 + lane/4,  n = (n''&3)*128 + (n''>>2)
#define SEC_IH0 0
#define SEC_HH0 8192
#define SEC_IH1 40960
#define SEC_HH1 73728
#define W_TOTAL 106496
__device__ uint32_t g_W[W_TOTAL];
__device__ float    g_bfrag[2 * 8 * 32 * 16];   // [L][wn][lane][16]

// ---------------- helpers ----------------
__device__ __forceinline__ uint32_t smem_u32(const void* p) {
    uint32_t a;
    asm("{ .reg .u64 t; cvta.to.shared.u64 t, %1; cvt.u32.u64 %0, t; }" : "=r"(a) : "l"(p));
    return a;
}
__device__ __forceinline__ void ldsm4(uint32_t* r, uint32_t addr) {
    asm volatile("ldmatrix.sync.aligned.m8n8.x4.shared.b16 {%0,%1,%2,%3}, [%4];"
                 : "=r"(r[0]), "=r"(r[1]), "=r"(r[2]), "=r"(r[3]) : "r"(addr));
}
__device__ __forceinline__ void mma16816(float* d, const uint32_t* a, uint32_t b0, uint32_t b1) {
    asm volatile("mma.sync.aligned.m16n8k16.row.col.f32.f16.f16.f32 "
                 "{%0,%1,%2,%3}, {%4,%5,%6,%7}, {%8,%9}, {%0,%1,%2,%3};"
                 : "+f"(d[0]), "+f"(d[1]), "+f"(d[2]), "+f"(d[3])
                 : "r"(a[0]), "r"(a[1]), "r"(a[2]), "r"(a[3]), "r"(b0), "r"(b1));
}
__device__ __forceinline__ float sigm(float x) {
    float e = __expf(-x);
    return __fdividef(1.0f, 1.0f + e);
}
__device__ __forceinline__ float tanha(float x) {
    float e = __expf(2.0f * x);
    return 1.0f - __fdividef(2.0f, e + 1.0f);
}
__device__ __forceinline__ uint32_t packh(__half a, __half b) {
    return (uint32_t)__half_as_ushort(a) | ((uint32_t)__half_as_ushort(b) << 16);
}

// ---------------- prep: weights -> fp16 B-fragments, bias -> C-fragments -------
__global__ void lstm_prep(const float* __restrict__ wih0, const float* __restrict__ whh0,
                          const float* __restrict__ bih0, const float* __restrict__ bhh0,
                          const float* __restrict__ wih1, const float* __restrict__ whh1,
                          const float* __restrict__ bih1, const float* __restrict__ bhh1) {
    int i = blockIdx.x * blockDim.x + threadIdx.x;
    if (i < W_TOTAL) {
        const float* W; int realK, KS, li;
        if      (i < SEC_HH0) { W = wih0; realK = INDIM; KS = 2; li = i; }
        else if (i < SEC_IH1) { W = whh0; realK = 128;   KS = 8; li = i - SEC_HH0; }
        else if (i < SEC_HH1) { W = wih1; realK = 128;   KS = 8; li = i - SEC_IH1; }
        else                  { W = whh1; realK = 128;   KS = 8; li = i - SEC_HH1; }
        int reg = li & 15, lane = (li >> 4) & 31;
        int ks = (li >> 9) % KS, wn = (li >> 9) / KS;
        int nf = reg >> 1, b = reg & 1;
        int npp = wn * 64 + nf * 8 + (lane >> 2);
        int n = (npp & 3) * 128 + (npp >> 2);
        int k0 = ks * 16 + (lane & 3) * 2 + b * 8;
        float w0 = (k0     < realK) ? W[n * realK + k0]     : 0.0f;
        float w1 = (k0 + 1 < realK) ? W[n * realK + k0 + 1] : 0.0f;
        g_W[i] = packh(__float2half_rn(w0), __float2half_rn(w1));
    } else if (i < W_TOTAL + 8192) {
        int li = i - W_TOTAL;
        int reg = li & 15, lane = (li >> 4) & 31, wn = (li >> 9) & 7, L = li >> 12;
        int npp = wn * 64 + (reg >> 1) * 8 + (lane & 3) * 2 + (reg & 1);
        int gj = (npp & 3) * 128 + (npp >> 2);
        g_bfrag[li] = L ? (bih1[gj] + bhh1[gj]) : (bih0[gj] + bhh0[gj]);
    }
}

// ---------------- K-loop: acc += A*W, full 64-col warp tile ---------------------
template <int KS>
__device__ __forceinline__ void mma_block(float (&acc)[2][8][4],
                                          const uint32_t* __restrict__ bw,
                                          uint32_t aBase, int stride)
{
    #pragma unroll
    for (int ks = 0; ks < KS; ks++) {
        const uint32_t* p = bw + ks * 512;
        uint32_t A0[4], A1[4];
        ldsm4(A0, aBase + ks * 32);
        ldsm4(A1, aBase + 16 * stride + ks * 32);
        #pragma unroll
        for (int h = 0; h < 2; h++) {
            uint4 B0 = *(const uint4*)(p + h * 8);
            uint4 B1 = *(const uint4*)(p + h * 8 + 4);
            uint32_t B[8] = {B0.x, B0.y, B0.z, B0.w, B1.x, B1.y, B1.z, B1.w};
            #pragma unroll
            for (int nf = 0; nf < 4; nf++) {
                mma16816(acc[0][h * 4 + nf], A0, B[nf * 2], B[nf * 2 + 1]);
                mma16816(acc[1][h * 4 + nf], A1, B[nf * 2], B[nf * 2 + 1]);
            }
        }
    }
}

__device__ __forceinline__ void init_bias(float (&acc)[2][8][4], int L, int wn, int lane) {
    const float4* bp = (const float4*)(g_bfrag + ((L * 8 + wn) * 32 + lane) * 16);
    float4 v0 = bp[0], v1 = bp[1], v2 = bp[2], v3 = bp[3];
    float bf[16] = {v0.x, v0.y, v0.z, v0.w, v1.x, v1.y, v1.z, v1.w,
                    v2.x, v2.y, v2.z, v2.w, v3.x, v3.y, v3.z, v3.w};
    #pragma unroll
    for (int mf = 0; mf < 2; mf++)
        #pragma unroll
        for (int nf = 0; nf < 8; nf++) {
            acc[mf][nf][0] = bf[nf * 2];
            acc[mf][nf][1] = bf[nf * 2 + 1];
            acc[mf][nf][2] = bf[nf * 2];
            acc[mf][nf][3] = bf[nf * 2 + 1];
        }
}

__device__ __forceinline__ void epilogue(float (&acc)[2][8][4], float (&cst)[16],
                                         int wn, int mg, int quad, int qid, bool ev, char* smc,
                                         uint32_t wTile, bool last,
                                         float* outH, float* outC, int b0)
{
    #pragma unroll
    for (int mf = 0; mf < 2; mf++)
        #pragma unroll
        for (int nf = 0; nf < 8; nf++) {
            float a0 = acc[mf][nf][0], a1 = acc[mf][nf][1];
            float a2 = acc[mf][nf][2], a3 = acc[mf][nf][3];
            float e1 = __shfl_xor_sync(0xffffffffu, ev ? a2 : a0, 1);
            float e2 = __shfl_xor_sync(0xffffffffu, ev ? a3 : a1, 1);
            float gi = ev ? a0 : e1;
            float gf = ev ? a1 : e2;
            float gg = ev ? e1 : a2;
            float go = ev ? e2 : a3;
            float cold = cst[mf * 8 + nf];
            float cn = sigm(gf) * cold + sigm(gi) * tanha(gg);
            cst[mf * 8 + nf] = cn;
            float h = sigm(go) * tanha(cn);
            int row = mg * 32 + mf * 16 + quad + (ev ? 0 : 8);
            int j = wn * 16 + nf * 2 + (qid >> 1);
            *(__half*)(smc + wTile + row * HSTRIDE + j * 2) = __float2half_rn(h);
            if (last) {
                outH[(size_t)(b0 + row) * HID + j] = h;
                outC[(size_t)(b0 + row) * HID + j] = cn;
            }
        }
}

// ---------------- main fused kernel ---------------------------------------------
__global__ __launch_bounds__(NT, 1)
void lstm_mma(const float* __restrict__ x,
              const float* __restrict__ fcw,
              const float* __restrict__ fcb,
              float* __restrict__ out)
{
    extern __shared__ __align__(128) char smc[];
    const uint32_t sb = smem_u32(smc);
    const int tid = threadIdx.x;
    const int wid = tid >> 5, lane = tid & 31;
    const int wn = wid & 7, mg = wid >> 3;
    const int quad = lane >> 2, qid = lane & 3;
    const bool ev = !(qid & 1);
    const int b0 = blockIdx.x * MR;

    // zero all smem (x pad cols + initial h state)
    for (int i = tid; i < SMEM_BYTES / 4; i += NT) ((uint32_t*)smc)[i] = 0;
    __syncthreads();

    // stage x(0) into buffer 0
    for (int i = tid; i < MR * INDIM; i += NT) {
        int r = i / INDIM, k = i - r * INDIM;
        float v = x[(size_t)(b0 + r) * (SEQ * INDIM) + k];
        *(__half*)(smc + SM_X + r * XSTRIDE + k * 2) = __float2half_rn(v);
    }
    __syncthreads();

    float cst0[16], cst1[16];
    #pragma unroll
    for (int i = 0; i < 16; i++) { cst0[i] = 0.0f; cst1[i] = 0.0f; }

    float* outLog = out;
    float* outH = out + (size_t)BATCH * OUTDIM;
    float* outC = outH + 2ull * BATCH * HID;

    const uint32_t laneH = (mg * 32 + (lane & 15)) * HSTRIDE + (lane >> 4) * 16;
    const uint32_t laneX = (mg * 32 + (lane & 15)) * XSTRIDE + (lane >> 4) * 16;

    const uint32_t* wIH0 = g_W + SEC_IH0 + (wn * 2) * 512 + lane * 16;
    const uint32_t* wHH0 = g_W + SEC_HH0 + (wn * 8) * 512 + lane * 16;
    const uint32_t* wIH1 = g_W + SEC_IH1 + (wn * 8) * 512 + lane * 16;
    const uint32_t* wHH1 = g_W + SEC_HH1 + (wn * 8) * 512 + lane * 16;

    for (int t = 0; t < SEQ; t++) {
        const int pb = t & 1;
        const bool last = (t == SEQ - 1);
        const uint32_t xb  = SM_X + pb * XBUF_SZ;
        const uint32_t h0r = HT_OFF(0, pb), h0w = HT_OFF(0, pb ^ 1);
        const uint32_t h1r = HT_OFF(1, pb), h1w = HT_OFF(1, pb ^ 1);

        // ============ LAYER 0 ============
        {
            float acc[2][8][4];
            init_bias(acc, 0, wn, lane);
            mma_block<2>(acc, wIH0, sb + xb + laneX, XSTRIDE);
            mma_block<8>(acc, wHH0, sb + h0r + laneH, HSTRIDE);
            epilogue(acc, cst0, wn, mg, quad, qid, ev, smc,
                     h0w, last, outH, outC, b0);
        }

        // ---- stage x(t+1) into the other buffer (ordered by the barrier below) ----
        if (t + 1 < SEQ) {
            const uint32_t xn = SM_X + (pb ^ 1) * XBUF_SZ;
            for (int i = tid; i < MR * INDIM; i += NT) {
                int r = i / INDIM, k = i - r * INDIM;
                float v = x[(size_t)(b0 + r) * (SEQ * INDIM) + (t + 1) * INDIM + k];
                *(__half*)(smc + xn + r * XSTRIDE + k * 2) = __float2half_rn(v);
            }
        }
        __syncthreads();   // h0(new) complete + x(t+1) staged

        // ============ LAYER 1 ============
        {
            float acc[2][8][4];
            init_bias(acc, 1, wn, lane);
            mma_block<8>(acc, wIH1, sb + h0w + laneH, HSTRIDE);
            mma_block<8>(acc, wHH1, sb + h1r + laneH, HSTRIDE);
            epilogue(acc, cst1, wn, mg, quad, qid, ev, smc,
                     h1w, last, outH + (size_t)BATCH * HID,
                     outC + (size_t)BATCH * HID, b0);
        }
        __syncthreads();   // h1(new) done before next step reads it
    }

    // ---- FC head from final h1 (buffer 0 after t=27) ----
    {
        const char* hT = smc + HT_OFF(1, 0);
        for (int i = tid; i < MR * OUTDIM; i += NT) {
            int r = i / OUTDIM, o = i - r * OUTDIM;
            float s = fcb[o];
            #pragma unroll 4
            for (int j = 0; j < HID; j++) {
                float hv = __half2float(*(const __half*)(hT + r * HSTRIDE + j * 2));
                s += hv * fcw[o * HID + j];
            }
            outLog[(size_t)(b0 + r) * OUTDIM + o] = s;
        }
    }
}

// ---------------- launch ----------------------------------------------------------
extern "C" void kernel_launch(void* const* d_in, const int* in_sizes, int n_in,
                              void* d_out, int out_size) {
    const float* x    = (const float*)d_in[0];
    const float* wih0 = (const float*)d_in[1];
    const float* whh0 = (const float*)d_in[2];
    const float* bih0 = (const float*)d_in[3];
    const float* bhh0 = (const float*)d_in[4];
    const float* wih1 = (const float*)d_in[5];
    const float* whh1 = (const float*)d_in[6];
    const float* bih1 = (const float*)d_in[7];
    const float* bhh1 = (const float*)d_in[8];
    const float* fcw  = (const float*)d_in[9];
    const float* fcb  = (const float*)d_in[10];

    lstm_prep<<<(W_TOTAL + 8192 + 255) / 256, 256>>>(wih0, whh0, bih0, bhh0,
                                                     wih1, whh1, bih1, bhh1);

    cudaFuncSetAttribute(lstm_mma, cudaFuncAttributeMaxDynamicSharedMemorySize, SMEM_BYTES);
    lstm_mma<<<BATCH / MR, NT, SMEM_BYTES>>>(x, fcw, fcb, (float*)d_out);
}

// round 13
// speedup vs baseline: 1.5273x; 1.5273x over previous
#include <cuda_runtime.h>
#include <cuda_fp16.h>
#include <stdint.h>
#include <math.h>

#define BATCH  16384
#define HID    128
#define SEQ    28
#define INDIM  28
#define OUTDIM 10
#define MR     32       // batch rows per CTA (2 CTAs/SM)
#define NT     256
#define HSTRIDE 272     // h tile row stride bytes (136 fp16) — ldsm conflict-free
#define XSTRIDE 80      // x tile row stride bytes
#define HT_SZ  (MR * HSTRIDE)            // 8704 B per h tile
#define SM_X   (4 * HT_SZ)               // x tiles after 4 h tiles
#define XBUF_SZ (MR * XSTRIDE)           // one x buffer
#define SMEM_BYTES (SM_X + 2 * XBUF_SZ)  // 39936

// h tile offset: layer L, buffer b
#define HT_OFF(L, b) (((L) * 2 + (b)) * HT_SZ)

// ---- prepped weights: exact mma.m16n8k16 B-fragment order, single fp16 ----
// layout per matrix section: [(c*8+wn)*KS + ks][lane][8 regs(uint32)]
// reg r = nf*2 + b : packed fp16 pair (k0, k0+1), k0 = ks*16 + (lane&3)*2 + b*8,
//                    n'' = wn*32 + nf*8 + lane/4,  n = (n''&3)*128 + c*64 + (n''>>2)
#define SEC_IH0 0
#define SEC_HH0 8192
#define SEC_IH1 40960
#define SEC_HH1 73728
#define W_TOTAL 106496
__device__ uint32_t g_W[W_TOTAL];
__device__ float    g_bfrag[2 * 2 * 8 * 32 * 8];   // [L][c][wn][lane][8]

// ---------------- helpers ----------------
__device__ __forceinline__ uint32_t smem_u32(const void* p) {
    uint32_t a;
    asm("{ .reg .u64 t; cvta.to.shared.u64 t, %1; cvt.u32.u64 %0, t; }" : "=r"(a) : "l"(p));
    return a;
}
__device__ __forceinline__ void ldsm4(uint32_t* r, uint32_t addr) {
    asm volatile("ldmatrix.sync.aligned.m8n8.x4.shared.b16 {%0,%1,%2,%3}, [%4];"
                 : "=r"(r[0]), "=r"(r[1]), "=r"(r[2]), "=r"(r[3]) : "r"(addr));
}
__device__ __forceinline__ void mma16816(float* d, const uint32_t* a, uint32_t b0, uint32_t b1) {
    asm volatile("mma.sync.aligned.m16n8k16.row.col.f32.f16.f16.f32 "
                 "{%0,%1,%2,%3}, {%4,%5,%6,%7}, {%8,%9}, {%0,%1,%2,%3};"
                 : "+f"(d[0]), "+f"(d[1]), "+f"(d[2]), "+f"(d[3])
                 : "r"(a[0]), "r"(a[1]), "r"(a[2]), "r"(a[3]), "r"(b0), "r"(b1));
}
__device__ __forceinline__ float sigm(float x) {
    float e = __expf(-x);
    return __fdividef(1.0f, 1.0f + e);
}
__device__ __forceinline__ float tanha(float x) {
    float e = __expf(2.0f * x);
    return 1.0f - __fdividef(2.0f, e + 1.0f);
}
__device__ __forceinline__ uint32_t packh(__half a, __half b) {
    return (uint32_t)__half_as_ushort(a) | ((uint32_t)__half_as_ushort(b) << 16);
}

// ---------------- prep: weights -> fp16 B-fragments, bias -> C-fragments -------
__global__ void lstm_prep(const float* __restrict__ wih0, const float* __restrict__ whh0,
                          const float* __restrict__ bih0, const float* __restrict__ bhh0,
                          const float* __restrict__ wih1, const float* __restrict__ whh1,
                          const float* __restrict__ bih1, const float* __restrict__ bhh1) {
    int i = blockIdx.x * blockDim.x + threadIdx.x;
    if (i < W_TOTAL) {
        const float* W; int realK, KS, li;
        if      (i < SEC_HH0) { W = wih0; realK = INDIM; KS = 2; li = i; }
        else if (i < SEC_IH1) { W = whh0; realK = 128;   KS = 8; li = i - SEC_HH0; }
        else if (i < SEC_HH1) { W = wih1; realK = 128;   KS = 8; li = i - SEC_IH1; }
        else                  { W = whh1; realK = 128;   KS = 8; li = i - SEC_HH1; }
        int reg = li & 7, lane = (li >> 3) & 31;
        int ks = (li >> 8) % KS, rest = (li >> 8) / KS;
        int wn = rest & 7, c = rest >> 3;
        int nf = reg >> 1, b = reg & 1;
        int npp = wn * 32 + nf * 8 + (lane >> 2);
        int n = (npp & 3) * 128 + c * 64 + (npp >> 2);
        int k0 = ks * 16 + (lane & 3) * 2 + b * 8;
        float w0 = (k0     < realK) ? W[n * realK + k0]     : 0.0f;
        float w1 = (k0 + 1 < realK) ? W[n * realK + k0 + 1] : 0.0f;
        g_W[i] = packh(__float2half_rn(w0), __float2half_rn(w1));
    } else if (i < W_TOTAL + 8192) {
        int li = i - W_TOTAL;
        int reg = li & 7, lane = (li >> 3) & 31, wn = (li >> 8) & 7, c = (li >> 11) & 1, L = li >> 12;
        int npp = wn * 32 + (reg >> 1) * 8 + (lane & 3) * 2 + (reg & 1);
        int gj = (npp & 3) * 128 + c * 64 + (npp >> 2);
        g_bfrag[li] = L ? (bih1[gj] + bhh1[gj]) : (bih0[gj] + bhh0[gj]);
    }
}

// -------- K-loop, both 32-col chunks fused: A loaded once per ks ---------------
template <int KS>
__device__ __forceinline__ void mma_block2(float (&acc)[2][2][4][4],
                                           const uint32_t* __restrict__ bw0,
                                           const uint32_t* __restrict__ bw1,
                                           uint32_t aBase, int stride)
{
    #pragma unroll
    for (int ks = 0; ks < KS; ks++) {
        uint32_t A0[4], A1[4];
        ldsm4(A0, aBase + ks * 32);
        ldsm4(A1, aBase + 16 * stride + ks * 32);
        #pragma unroll
        for (int c = 0; c < 2; c++) {
            const uint32_t* p = (c ? bw1 : bw0) + ks * 256;
            uint4 B0 = *(const uint4*)(p);
            uint4 B1 = *(const uint4*)(p + 4);
            uint32_t B[8] = {B0.x, B0.y, B0.z, B0.w, B1.x, B1.y, B1.z, B1.w};
            #pragma unroll
            for (int nf = 0; nf < 4; nf++) {
                mma16816(acc[c][0][nf], A0, B[nf * 2], B[nf * 2 + 1]);
                mma16816(acc[c][1][nf], A1, B[nf * 2], B[nf * 2 + 1]);
            }
        }
    }
}

__device__ __forceinline__ void init_bias(float (&acc)[2][4][4], int L, int c, int wn, int lane) {
    const float4* bp = (const float4*)(g_bfrag + (((L * 2 + c) * 8 + wn) * 32 + lane) * 8);
    float4 v0 = bp[0], v1 = bp[1];
    float bf[8] = {v0.x, v0.y, v0.z, v0.w, v1.x, v1.y, v1.z, v1.w};
    #pragma unroll
    for (int mf = 0; mf < 2; mf++)
        #pragma unroll
        for (int nf = 0; nf < 4; nf++) {
            acc[mf][nf][0] = bf[nf * 2];
            acc[mf][nf][1] = bf[nf * 2 + 1];
            acc[mf][nf][2] = bf[nf * 2];
            acc[mf][nf][3] = bf[nf * 2 + 1];
        }
}

__device__ __forceinline__ void epilogue(float (&acc)[2][4][4], float (&cst)[32], int cbase,
                                         int c, int wn, int quad, int qid, bool ev, char* smc,
                                         uint32_t wTile, bool last,
                                         float* outH, float* outC, int b0)
{
    #pragma unroll
    for (int mf = 0; mf < 2; mf++)
        #pragma unroll
        for (int nf = 0; nf < 4; nf++) {
            float a0 = acc[mf][nf][0], a1 = acc[mf][nf][1];
            float a2 = acc[mf][nf][2], a3 = acc[mf][nf][3];
            float e1 = __shfl_xor_sync(0xffffffffu, ev ? a2 : a0, 1);
            float e2 = __shfl_xor_sync(0xffffffffu, ev ? a3 : a1, 1);
            float gi = ev ? a0 : e1;
            float gf = ev ? a1 : e2;
            float gg = ev ? e1 : a2;
            float go = ev ? e2 : a3;
            float cold = cst[cbase + mf * 4 + nf];
            float cn = sigm(gf) * cold + sigm(gi) * tanha(gg);
            cst[cbase + mf * 4 + nf] = cn;
            float h = sigm(go) * tanha(cn);
            int row = mf * 16 + quad + (ev ? 0 : 8);
            int j = c * 64 + wn * 8 + nf * 2 + (qid >> 1);
            *(__half*)(smc + wTile + row * HSTRIDE + j * 2) = __float2half_rn(h);
            if (last) {
                outH[(size_t)(b0 + row) * HID + j] = h;
                outC[(size_t)(b0 + row) * HID + j] = cn;
            }
        }
}

// ---------------- main fused kernel ---------------------------------------------
__global__ __launch_bounds__(NT, 2)
void lstm_mma(const float* __restrict__ x,
              const float* __restrict__ fcw,
              const float* __restrict__ fcb,
              float* __restrict__ out)
{
    extern __shared__ __align__(128) char smc[];
    const uint32_t sb = smem_u32(smc);
    const int tid = threadIdx.x;
    const int wn = tid >> 5, lane = tid & 31;
    const int quad = lane >> 2, qid = lane & 3;
    const bool ev = !(qid & 1);
    const int b0 = blockIdx.x * MR;

    // zero all smem (x pad cols + initial h state)
    for (int i = tid; i < SMEM_BYTES / 4; i += NT) ((uint32_t*)smc)[i] = 0;
    __syncthreads();

    // stage x(0) into buffer 0
    for (int i = tid; i < MR * INDIM; i += NT) {
        int r = i / INDIM, k = i - r * INDIM;
        float v = x[(size_t)(b0 + r) * (SEQ * INDIM) + k];
        *(__half*)(smc + SM_X + r * XSTRIDE + k * 2) = __float2half_rn(v);
    }
    __syncthreads();

    float cst[32];
    #pragma unroll
    for (int i = 0; i < 32; i++) cst[i] = 0.0f;

    float* outLog = out;
    float* outH = out + (size_t)BATCH * OUTDIM;
    float* outC = outH + 2ull * BATCH * HID;

    const uint32_t laneH = (lane & 15) * HSTRIDE + (lane >> 4) * 16;
    const uint32_t laneX = (lane & 15) * XSTRIDE + (lane >> 4) * 16;

    // per-chunk weight fragment base pointers
    const uint32_t* wIH0c0 = g_W + SEC_IH0 + ((0 * 8 + wn) * 2) * 256 + lane * 8;
    const uint32_t* wIH0c1 = g_W + SEC_IH0 + ((1 * 8 + wn) * 2) * 256 + lane * 8;
    const uint32_t* wHH0c0 = g_W + SEC_HH0 + ((0 * 8 + wn) * 8) * 256 + lane * 8;
    const uint32_t* wHH0c1 = g_W + SEC_HH0 + ((1 * 8 + wn) * 8) * 256 + lane * 8;
    const uint32_t* wIH1c0 = g_W + SEC_IH1 + ((0 * 8 + wn) * 8) * 256 + lane * 8;
    const uint32_t* wIH1c1 = g_W + SEC_IH1 + ((1 * 8 + wn) * 8) * 256 + lane * 8;
    const uint32_t* wHH1c0 = g_W + SEC_HH1 + ((0 * 8 + wn) * 8) * 256 + lane * 8;
    const uint32_t* wHH1c1 = g_W + SEC_HH1 + ((1 * 8 + wn) * 8) * 256 + lane * 8;

    for (int t = 0; t < SEQ; t++) {
        const int pb = t & 1;
        const bool last = (t == SEQ - 1);
        const uint32_t xb  = SM_X + pb * XBUF_SZ;
        const uint32_t h0r = HT_OFF(0, pb), h0w = HT_OFF(0, pb ^ 1);
        const uint32_t h1r = HT_OFF(1, pb), h1w = HT_OFF(1, pb ^ 1);

        // ============ LAYER 0 ============
        {
            float acc[2][2][4][4];
            init_bias(acc[0], 0, 0, wn, lane);
            init_bias(acc[1], 0, 1, wn, lane);
            mma_block2<2>(acc, wIH0c0, wIH0c1, sb + xb + laneX, XSTRIDE);
            mma_block2<8>(acc, wHH0c0, wHH0c1, sb + h0r + laneH, HSTRIDE);
            epilogue(acc[0], cst, 0, 0, wn, quad, qid, ev, smc, h0w, last, outH, outC, b0);
            epilogue(acc[1], cst, 8, 1, wn, quad, qid, ev, smc, h0w, last, outH, outC, b0);
        }

        // ---- stage x(t+1) into the other buffer (ordered by the barrier below) ----
        if (t + 1 < SEQ) {
            const uint32_t xn = SM_X + (pb ^ 1) * XBUF_SZ;
            for (int i = tid; i < MR * INDIM; i += NT) {
                int r = i / INDIM, k = i - r * INDIM;
                float v = x[(size_t)(b0 + r) * (SEQ * INDIM) + (t + 1) * INDIM + k];
                *(__half*)(smc + xn + r * XSTRIDE + k * 2) = __float2half_rn(v);
            }
        }
        __syncthreads();   // h0(new) complete + x(t+1) staged

        // ============ LAYER 1 ============
        {
            float acc[2][2][4][4];
            init_bias(acc[0], 1, 0, wn, lane);
            init_bias(acc[1], 1, 1, wn, lane);
            mma_block2<8>(acc, wIH1c0, wIH1c1, sb + h0w + laneH, HSTRIDE);
            mma_block2<8>(acc, wHH1c0, wHH1c1, sb + h1r + laneH, HSTRIDE);
            epilogue(acc[0], cst, 16, 0, wn, quad, qid, ev, smc, h1w, last,
                     outH + (size_t)BATCH * HID, outC + (size_t)BATCH * HID, b0);
            epilogue(acc[1], cst, 24, 1, wn, quad, qid, ev, smc, h1w, last,
                     outH + (size_t)BATCH * HID, outC + (size_t)BATCH * HID, b0);
        }
        __syncthreads();   // h1(new) done before next step reads it
    }

    // ---- FC head from final h1 (buffer 0 after t=27) ----
    {
        const char* hT = smc + HT_OFF(1, 0);
        for (int i = tid; i < MR * OUTDIM; i += NT) {
            int r = i / OUTDIM, o = i - r * OUTDIM;
            float s = fcb[o];
            #pragma unroll 4
            for (int j = 0; j < HID; j++) {
                float hv = __half2float(*(const __half*)(hT + r * HSTRIDE + j * 2));
                s += hv * fcw[o * HID + j];
            }
            outLog[(size_t)(b0 + r) * OUTDIM + o] = s;
        }
    }
}

// ---------------- launch ----------------------------------------------------------
extern "C" void kernel_launch(void* const* d_in, const int* in_sizes, int n_in,
                              void* d_out, int out_size) {
    const float* x    = (const float*)d_in[0];
    const float* wih0 = (const float*)d_in[1];
    const float* whh0 = (const float*)d_in[2];
    const float* bih0 = (const float*)d_in[3];
    const float* bhh0 = (const float*)d_in[4];
    const float* wih1 = (const float*)d_in[5];
    const float* whh1 = (const float*)d_in[6];
    const float* bih1 = (const float*)d_in[7];
    const float* bhh1 = (const float*)d_in[8];
    const float* fcw  = (const float*)d_in[9];
    const float* fcb  = (const float*)d_in[10];

    lstm_prep<<<(W_TOTAL + 8192 + 255) / 256, 256>>>(wih0, whh0, bih0, bhh0,
                                                     wih1, whh1, bih1, bhh1);

    cudaFuncSetAttribute(lstm_mma, cudaFuncAttributeMaxDynamicSharedMemorySize, SMEM_BYTES);
    lstm_mma<<<BATCH / MR, NT, SMEM_BYTES>>>(x, fcw, fcb, (float*)d_out);
}

// round 14
// speedup vs baseline: 1.6083x; 1.0530x over previous
#include <cuda_runtime.h>
#include <cuda_fp16.h>
#include <stdint.h>
#include <math.h>

#define BATCH  16384
#define HID    128
#define SEQ    28
#define INDIM  28
#define OUTDIM 10
#define MR     32       // batch rows per CTA (2 CTAs/SM)
#define NT     256
#define HSTRIDE 272     // h tile row stride bytes (136 fp16) — ldsm conflict-free
#define XSTRIDE 80      // x tile row stride bytes
#define HT_SZ  (MR * HSTRIDE)            // 8704 B per h tile
#define SM_X   (4 * HT_SZ)               // x tiles after 4 h tiles
#define XBUF_SZ (MR * XSTRIDE)           // one x buffer
#define SMEM_BYTES (SM_X + 2 * XBUF_SZ)  // 39936

// h tile offset: layer L, buffer b
#define HT_OFF(L, b) (((L) * 2 + (b)) * HT_SZ)

// ---- prepped weights: exact mma.m16n8k16 B-fragment order, single fp16 ----
#define SEC_IH0 0
#define SEC_HH0 8192
#define SEC_IH1 40960
#define SEC_HH1 73728
#define W_TOTAL 106496
__device__ uint32_t g_W[W_TOTAL];
__device__ float    g_bfrag[2 * 2 * 8 * 32 * 8];   // [L][c][wn][lane][8]

// ---------------- helpers ----------------
__device__ __forceinline__ uint32_t smem_u32(const void* p) {
    uint32_t a;
    asm("{ .reg .u64 t; cvta.to.shared.u64 t, %1; cvt.u32.u64 %0, t; }" : "=r"(a) : "l"(p));
    return a;
}
__device__ __forceinline__ void ldsm4(uint32_t* r, uint32_t addr) {
    asm volatile("ldmatrix.sync.aligned.m8n8.x4.shared.b16 {%0,%1,%2,%3}, [%4];"
                 : "=r"(r[0]), "=r"(r[1]), "=r"(r[2]), "=r"(r[3]) : "r"(addr));
}
__device__ __forceinline__ void mma16816(float* d, const uint32_t* a, uint32_t b0, uint32_t b1) {
    asm volatile("mma.sync.aligned.m16n8k16.row.col.f32.f16.f16.f32 "
                 "{%0,%1,%2,%3}, {%4,%5,%6,%7}, {%8,%9}, {%0,%1,%2,%3};"
                 : "+f"(d[0]), "+f"(d[1]), "+f"(d[2]), "+f"(d[3])
                 : "r"(a[0]), "r"(a[1]), "r"(a[2]), "r"(a[3]), "r"(b0), "r"(b1));
}
__device__ __forceinline__ float sigm(float x) {
    float e = __expf(-x);
    return __fdividef(1.0f, 1.0f + e);
}
__device__ __forceinline__ float tanha(float x) {
    float e = __expf(2.0f * x);
    return 1.0f - __fdividef(2.0f, e + 1.0f);
}
__device__ __forceinline__ uint32_t packh(__half a, __half b) {
    return (uint32_t)__half_as_ushort(a) | ((uint32_t)__half_as_ushort(b) << 16);
}

// ---------------- prep: weights -> fp16 B-fragments, bias -> C-fragments -------
__global__ void lstm_prep(const float* __restrict__ wih0, const float* __restrict__ whh0,
                          const float* __restrict__ bih0, const float* __restrict__ bhh0,
                          const float* __restrict__ wih1, const float* __restrict__ whh1,
                          const float* __restrict__ bih1, const float* __restrict__ bhh1) {
    int i = blockIdx.x * blockDim.x + threadIdx.x;
    if (i < W_TOTAL) {
        const float* W; int realK, KS, li;
        if      (i < SEC_HH0) { W = wih0; realK = INDIM; KS = 2; li = i; }
        else if (i < SEC_IH1) { W = whh0; realK = 128;   KS = 8; li = i - SEC_HH0; }
        else if (i < SEC_HH1) { W = wih1; realK = 128;   KS = 8; li = i - SEC_IH1; }
        else                  { W = whh1; realK = 128;   KS = 8; li = i - SEC_HH1; }
        int reg = li & 7, lane = (li >> 3) & 31;
        int ks = (li >> 8) % KS, rest = (li >> 8) / KS;
        int wn = rest & 7, c = rest >> 3;
        int nf = reg >> 1, b = reg & 1;
        int npp = wn * 32 + nf * 8 + (lane >> 2);
        int n = (npp & 3) * 128 + c * 64 + (npp >> 2);
        int k0 = ks * 16 + (lane & 3) * 2 + b * 8;
        float w0 = (k0     < realK) ? W[n * realK + k0]     : 0.0f;
        float w1 = (k0 + 1 < realK) ? W[n * realK + k0 + 1] : 0.0f;
        g_W[i] = packh(__float2half_rn(w0), __float2half_rn(w1));
    } else if (i < W_TOTAL + 8192) {
        int li = i - W_TOTAL;
        int reg = li & 7, lane = (li >> 3) & 31, wn = (li >> 8) & 7, c = (li >> 11) & 1, L = li >> 12;
        int npp = wn * 32 + (reg >> 1) * 8 + (lane & 3) * 2 + (reg & 1);
        int gj = (npp & 3) * 128 + c * 64 + (npp >> 2);
        g_bfrag[li] = L ? (bih1[gj] + bhh1[gj]) : (bih0[gj] + bhh0[gj]);
    }
}

// -------- K-loop, both 32-col chunks fused: A loaded once per ks ---------------
template <int KS>
__device__ __forceinline__ void mma_block2(float (&acc)[2][2][4][4],
                                           const uint32_t* __restrict__ bw0,
                                           const uint32_t* __restrict__ bw1,
                                           uint32_t aBase, int stride)
{
    #pragma unroll
    for (int ks = 0; ks < KS; ks++) {
        uint32_t A0[4], A1[4];
        ldsm4(A0, aBase + ks * 32);
        ldsm4(A1, aBase + 16 * stride + ks * 32);
        #pragma unroll
        for (int c = 0; c < 2; c++) {
            const uint32_t* p = (c ? bw1 : bw0) + ks * 256;
            uint4 B0 = *(const uint4*)(p);
            uint4 B1 = *(const uint4*)(p + 4);
            uint32_t B[8] = {B0.x, B0.y, B0.z, B0.w, B1.x, B1.y, B1.z, B1.w};
            #pragma unroll
            for (int nf = 0; nf < 4; nf++) {
                mma16816(acc[c][0][nf], A0, B[nf * 2], B[nf * 2 + 1]);
                mma16816(acc[c][1][nf], A1, B[nf * 2], B[nf * 2 + 1]);
            }
        }
    }
}

__device__ __forceinline__ void init_bias(float (&acc)[2][4][4], int L, int c, int wn, int lane) {
    const float4* bp = (const float4*)(g_bfrag + (((L * 2 + c) * 8 + wn) * 32 + lane) * 8);
    float4 v0 = bp[0], v1 = bp[1];
    float bf[8] = {v0.x, v0.y, v0.z, v0.w, v1.x, v1.y, v1.z, v1.w};
    #pragma unroll
    for (int mf = 0; mf < 2; mf++)
        #pragma unroll
        for (int nf = 0; nf < 4; nf++) {
            acc[mf][nf][0] = bf[nf * 2];
            acc[mf][nf][1] = bf[nf * 2 + 1];
            acc[mf][nf][2] = bf[nf * 2];
            acc[mf][nf][3] = bf[nf * 2 + 1];
        }
}

__device__ __forceinline__ void epilogue(float (&acc)[2][4][4], float (&cst)[32], int cbase,
                                         int c, int wn, int quad, int qid, bool ev, char* smc,
                                         uint32_t wTile, bool last,
                                         float* outH, float* outC, int b0)
{
    #pragma unroll
    for (int mf = 0; mf < 2; mf++)
        #pragma unroll
        for (int nf = 0; nf < 4; nf++) {
            float a0 = acc[mf][nf][0], a1 = acc[mf][nf][1];
            float a2 = acc[mf][nf][2], a3 = acc[mf][nf][3];
            float e1 = __shfl_xor_sync(0xffffffffu, ev ? a2 : a0, 1);
            float e2 = __shfl_xor_sync(0xffffffffu, ev ? a3 : a1, 1);
            float gi = ev ? a0 : e1;
            float gf = ev ? a1 : e2;
            float gg = ev ? e1 : a2;
            float go = ev ? e2 : a3;
            float cold = cst[cbase + mf * 4 + nf];
            float cn = sigm(gf) * cold + sigm(gi) * tanha(gg);
            cst[cbase + mf * 4 + nf] = cn;
            float h = sigm(go) * tanha(cn);
            int row = mf * 16 + quad + (ev ? 0 : 8);
            int j = c * 64 + wn * 8 + nf * 2 + (qid >> 1);
            *(__half*)(smc + wTile + row * HSTRIDE + j * 2) = __float2half_rn(h);
            if (last) {
                outH[(size_t)(b0 + row) * HID + j] = h;
                outC[(size_t)(b0 + row) * HID + j] = cn;
            }
        }
}

// ---------------- main fused kernel ---------------------------------------------
__global__ __launch_bounds__(NT, 2)
void lstm_mma(const float* __restrict__ x,
              const float* __restrict__ fcw,
              const float* __restrict__ fcb,
              float* __restrict__ out)
{
    extern __shared__ __align__(128) char smc[];
    const uint32_t sb = smem_u32(smc);
    const int tid = threadIdx.x;
    const int wn = tid >> 5, lane = tid & 31;
    const int quad = lane >> 2, qid = lane & 3;
    const bool ev = !(qid & 1);
    const int b0 = blockIdx.x * MR;

    // zero all smem (x pad cols + initial h state)
    for (int i = tid; i < SMEM_BYTES / 4; i += NT) ((uint32_t*)smc)[i] = 0;
    __syncthreads();

    // stage x(0) -> buf0, x(1) -> buf1
    for (int i = tid; i < MR * INDIM; i += NT) {
        int r = i / INDIM, k = i - r * INDIM;
        const float* xr = x + (size_t)(b0 + r) * (SEQ * INDIM) + k;
        *(__half*)(smc + SM_X + r * XSTRIDE + k * 2)            = __float2half_rn(xr[0]);
        *(__half*)(smc + SM_X + XBUF_SZ + r * XSTRIDE + k * 2)  = __float2half_rn(xr[INDIM]);
    }
    __syncthreads();

    float cst[32];
    #pragma unroll
    for (int i = 0; i < 32; i++) cst[i] = 0.0f;

    float* outLog = out;
    float* outH = out + (size_t)BATCH * OUTDIM;
    float* outC = outH + 2ull * BATCH * HID;
    float* outH1 = outH + (size_t)BATCH * HID;
    float* outC1 = outC + (size_t)BATCH * HID;

    const uint32_t laneH = (lane & 15) * HSTRIDE + (lane >> 4) * 16;
    const uint32_t laneX = (lane & 15) * XSTRIDE + (lane >> 4) * 16;

    // per-chunk weight fragment base pointers
    const uint32_t* wIH0c0 = g_W + SEC_IH0 + ((0 * 8 + wn) * 2) * 256 + lane * 8;
    const uint32_t* wIH0c1 = g_W + SEC_IH0 + ((1 * 8 + wn) * 2) * 256 + lane * 8;
    const uint32_t* wHH0c0 = g_W + SEC_HH0 + ((0 * 8 + wn) * 8) * 256 + lane * 8;
    const uint32_t* wHH0c1 = g_W + SEC_HH0 + ((1 * 8 + wn) * 8) * 256 + lane * 8;
    const uint32_t* wIH1c0 = g_W + SEC_IH1 + ((0 * 8 + wn) * 8) * 256 + lane * 8;
    const uint32_t* wIH1c1 = g_W + SEC_IH1 + ((1 * 8 + wn) * 8) * 256 + lane * 8;
    const uint32_t* wHH1c0 = g_W + SEC_HH1 + ((0 * 8 + wn) * 8) * 256 + lane * 8;
    const uint32_t* wHH1c1 = g_W + SEC_HH1 + ((1 * 8 + wn) * 8) * 256 + lane * 8;

    // ---- prologue: L0(0): reads x buf0 + h0 buf0 (zeros), writes h0 buf1 ----
    {
        float acc[2][2][4][4];
        init_bias(acc[0], 0, 0, wn, lane);
        init_bias(acc[1], 0, 1, wn, lane);
        mma_block2<2>(acc, wIH0c0, wIH0c1, sb + SM_X + laneX, XSTRIDE);
        mma_block2<8>(acc, wHH0c0, wHH0c1, sb + HT_OFF(0, 0) + laneH, HSTRIDE);
        epilogue(acc[0], cst, 0, 0, wn, quad, qid, ev, smc, HT_OFF(0, 1), false, outH, outC, b0);
        epilogue(acc[1], cst, 8, 1, wn, quad, qid, ev, smc, HT_OFF(0, 1), false, outH, outC, b0);
    }

    // ---- main loop: ONE barrier per timestep; interval t = { L1(t), L0(t+1) } ----
    for (int t = 0; t < SEQ; t++) {
        const int pb = t & 1;
        __syncthreads();   // h0(t) [buf pb^1] + h1(t-1) [buf pb] + x(t+1) all visible

        // stage x(t+2) into buf[t&1] (its old content consumed by L0(t) last interval)
        if (t + 2 < SEQ) {
            const uint32_t xn = SM_X + pb * XBUF_SZ;
            for (int i = tid; i < MR * INDIM; i += NT) {
                int r = i / INDIM, k = i - r * INDIM;
                float v = x[(size_t)(b0 + r) * (SEQ * INDIM) + (t + 2) * INDIM + k];
                *(__half*)(smc + xn + r * XSTRIDE + k * 2) = __float2half_rn(v);
            }
        }

        // ---- L1(t): reads h0 buf[pb^1], h1 buf[pb]; writes h1 buf[pb^1] ----
        {
            const bool last1 = (t == SEQ - 1);
            float acc[2][2][4][4];
            init_bias(acc[0], 1, 0, wn, lane);
            init_bias(acc[1], 1, 1, wn, lane);
            mma_block2<8>(acc, wIH1c0, wIH1c1, sb + HT_OFF(1, pb ^ 1) - HT_SZ * 2 + laneH, HSTRIDE);
            // NOTE: HT_OFF(1,b)-2*HT_SZ == HT_OFF(0,b); keep it explicit instead:
            // (left as direct call below)
            mma_block2<8>(acc, wHH1c0, wHH1c1, sb + HT_OFF(1, pb) + laneH, HSTRIDE);
            epilogue(acc[0], cst, 16, 0, wn, quad, qid, ev, smc, HT_OFF(1, pb ^ 1), last1, outH1, outC1, b0);
            epilogue(acc[1], cst, 24, 1, wn, quad, qid, ev, smc, HT_OFF(1, pb ^ 1), last1, outH1, outC1, b0);
        }

        // ---- L0(t+1): reads x buf[(t+1)&1], h0 buf[pb^1]; writes h0 buf[pb] ----
        if (t + 1 < SEQ) {
            const bool last0 = (t + 1 == SEQ - 1);
            float acc[2][2][4][4];
            init_bias(acc[0], 0, 0, wn, lane);
            init_bias(acc[1], 0, 1, wn, lane);
            mma_block2<2>(acc, wIH0c0, wIH0c1,
                          sb + SM_X + ((t + 1) & 1) * XBUF_SZ + laneX, XSTRIDE);
            mma_block2<8>(acc, wHH0c0, wHH0c1, sb + HT_OFF(0, pb ^ 1) + laneH, HSTRIDE);
            epilogue(acc[0], cst, 0, 0, wn, quad, qid, ev, smc, HT_OFF(0, pb), last0, outH, outC, b0);
            epilogue(acc[1], cst, 8, 1, wn, quad, qid, ev, smc, HT_OFF(0, pb), last0, outH, outC, b0);
        }
    }
    __syncthreads();

    // ---- FC head from final h1 (buffer 0 after t=27) ----
    {
        const char* hT = smc + HT_OFF(1, 0);
        for (int i = tid; i < MR * OUTDIM; i += NT) {
            int r = i / OUTDIM, o = i - r * OUTDIM;
            float s = fcb[o];
            #pragma unroll 4
            for (int j = 0; j < HID; j++) {
                float hv = __half2float(*(const __half*)(hT + r * HSTRIDE + j * 2));
                s += hv * fcw[o * HID + j];
            }
            outLog[(size_t)(b0 + r) * OUTDIM + o] = s;
        }
    }
}

// ---------------- launch ----------------------------------------------------------
extern "C" void kernel_launch(void* const* d_in, const int* in_sizes, int n_in,
                              void* d_out, int out_size) {
    const float* x    = (const float*)d_in[0];
    const float* wih0 = (const float*)d_in[1];
    const float* whh0 = (const float*)d_in[2];
    const float* bih0 = (const float*)d_in[3];
    const float* bhh0 = (const float*)d_in[4];
    const float* wih1 = (const float*)d_in[5];
    const float* whh1 = (const float*)d_in[6];
    const float* bih1 = (const float*)d_in[7];
    const float* bhh1 = (const float*)d_in[8];
    const float* fcw  = (const float*)d_in[9];
    const float* fcb  = (const float*)d_in[10];

    lstm_prep<<<(W_TOTAL + 8192 + 255) / 256, 256>>>(wih0, whh0, bih0, bhh0,
                                                     wih1, whh1, bih1, bhh1);

    cudaFuncSetAttribute(lstm_mma, cudaFuncAttributeMaxDynamicSharedMemorySize, SMEM_BYTES);
    lstm_mma<<<BATCH / MR, NT, SMEM_BYTES>>>(x, fcw, fcb, (float*)d_out);
}